// round 3
// baseline (speedup 1.0000x reference)
#include <cuda_runtime.h>
#include <cstdint>

// TopKRouter: logits = x @ W + b ; softmax over E=64 ; top-2 (idx, vals)
// x: (16384, 2048) fp32, W: (2048, 64) fp32, b: (64,)
// out (float32): [0..2M) = topk_idx as float (M,2) ; [2M..4M) = topk_vals (M,2)

#define DK 2048
#define NE 64
#define KC 64
#define MT 32
#define NTHREADS 128
#define NCHUNK (DK / KC)   // 32

__device__ __forceinline__ unsigned long long fma2(unsigned long long a,
                                                   unsigned long long b,
                                                   unsigned long long c) {
    unsigned long long d;
    asm("fma.rn.f32x2 %0, %1, %2, %3;" : "=l"(d) : "l"(a), "l"(b), "l"(c));
    return d;
}
__device__ __forceinline__ float2 unpk(unsigned long long v) {
    float2 f;
    asm("mov.b64 {%0, %1}, %2;" : "=f"(f.x), "=f"(f.y) : "l"(v));
    return f;
}
__device__ __forceinline__ uint32_t su32(const void* p) {
    uint32_t a;
    asm("{ .reg .u64 t; cvta.to.shared.u64 t, %1; cvt.u32.u64 %0, t; }"
        : "=r"(a) : "l"(p));
    return a;
}
__device__ __forceinline__ void cp_async16(uint32_t saddr, const void* g) {
    asm volatile("cp.async.cg.shared.global [%0], [%1], 16;" :: "r"(saddr), "l"(g));
}
#define CP_COMMIT() asm volatile("cp.async.commit_group;" ::: "memory")
#define CP_WAIT0()  asm volatile("cp.async.wait_group 0;" ::: "memory")

__global__ __launch_bounds__(NTHREADS, 3)
void router_kernel(const float* __restrict__ x,
                   const float* __restrict__ W,
                   const float* __restrict__ bias,
                   float* __restrict__ out,
                   int M)
{
    extern __shared__ float sm[];
    // Xdup buffers: [MT][2*KC] (each x value duplicated -> (x,x) pairs), 4096 floats each
    // W buffers:    [KC][NE],                                            4096 floats each
    float* XSb[2] = { sm,        sm + 4096 };
    float* WSb[2] = { sm + 8192, sm + 12288 };
    const uint32_t wsu[2] = { su32(WSb[0]), su32(WSb[1]) };

    const int tid = threadIdx.x;
    const int tm4 = (tid >> 4) * 4;     // token base in tile (0..28)
    const int te4 = (tid & 15) * 4;     // expert base (0..60)
    const int m0  = blockIdx.x * MT;

    const int sidx = tid;               // staging: 4 float4 per thread for X, 8 for W
    const int sm_tok0 = sidx >> 4;      // reused pattern below

    unsigned long long acc[4][2];
#pragma unroll
    for (int i = 0; i < 4; i++) { acc[i][0] = 0ull; acc[i][1] = 0ull; }

    // ---- prologue: stage chunk 0 into buffer 0 ----
    {
        const float4* wg = (const float4*)W;    // chunk 0 of W is contiguous
#pragma unroll
        for (int r = 0; r < 8; r++)
            cp_async16(wsu[0] + (uint32_t)(tid + r * 128) * 16, wg + tid + r * 128);
        CP_COMMIT();
#pragma unroll
        for (int r = 0; r < 4; r++) {
            int idx = tid + r * 128;
            int m = idx >> 4, kq = idx & 15;
            float4 v = *(const float4*)(x + (size_t)(m0 + m) * DK + kq * 4);
            float* dst = &XSb[0][m * (2 * KC) + kq * 8];
            *(float4*)dst       = make_float4(v.x, v.x, v.y, v.y);
            *(float4*)(dst + 4) = make_float4(v.z, v.z, v.w, v.w);
        }
        CP_WAIT0();
        __syncthreads();
    }

    // ---- main loop: 1 barrier per chunk, double-buffered ----
    for (int c = 0; c < NCHUNK; ++c) {
        const int p = c & 1, q = p ^ 1;
        const bool more = (c + 1 < NCHUNK);

        float4 xr[4];
        if (more) {
            // issue next W chunk (cp.async) and next X chunk (LDG) early
            const float4* wg = (const float4*)(W + (size_t)(c + 1) * KC * NE);
#pragma unroll
            for (int r = 0; r < 8; r++)
                cp_async16(wsu[q] + (uint32_t)(tid + r * 128) * 16, wg + tid + r * 128);
            CP_COMMIT();
#pragma unroll
            for (int r = 0; r < 4; r++) {
                int idx = tid + r * 128;
                int m = idx >> 4, kq = idx & 15;
                xr[r] = *(const float4*)(x + (size_t)(m0 + m) * DK
                                           + (size_t)(c + 1) * KC + kq * 4);
            }
        }

        // compute chunk c from buffer p
        const float* xs  = XSb[p];
        const float* wsp = WSb[p];
#pragma unroll
        for (int kc = 0; kc < KC; kc += 4) {
            ulonglong2 wv[4];
#pragma unroll
            for (int j = 0; j < 4; j++)
                wv[j] = *(const ulonglong2*)&wsp[(kc + j) * NE + te4];
#pragma unroll
            for (int i = 0; i < 4; i++) {
                ulonglong2 x0 = *(const ulonglong2*)&xs[(tm4 + i) * (2 * KC) + 2 * kc];
                ulonglong2 x1 = *(const ulonglong2*)&xs[(tm4 + i) * (2 * KC) + 2 * kc + 4];
                acc[i][0] = fma2(x0.x, wv[0].x, acc[i][0]);
                acc[i][1] = fma2(x0.x, wv[0].y, acc[i][1]);
                acc[i][0] = fma2(x0.y, wv[1].x, acc[i][0]);
                acc[i][1] = fma2(x0.y, wv[1].y, acc[i][1]);
                acc[i][0] = fma2(x1.x, wv[2].x, acc[i][0]);
                acc[i][1] = fma2(x1.x, wv[2].y, acc[i][1]);
                acc[i][0] = fma2(x1.y, wv[3].x, acc[i][0]);
                acc[i][1] = fma2(x1.y, wv[3].y, acc[i][1]);
            }
        }

        if (more) {
            // store duplicated X for chunk c+1 into buffer q
            float* xd = XSb[q];
#pragma unroll
            for (int r = 0; r < 4; r++) {
                int idx = tid + r * 128;
                int m = idx >> 4, kq = idx & 15;
                float4 v = xr[r];
                float* dst = &xd[m * (2 * KC) + kq * 8];
                *(float4*)dst       = make_float4(v.x, v.x, v.y, v.y);
                *(float4*)(dst + 4) = make_float4(v.z, v.z, v.w, v.w);
            }
            CP_WAIT0();
            __syncthreads();
        }
    }

    __syncthreads();   // all compute reads done; smem now reused for logits

    // write logits (+bias) into smem [MT][NE+4]
    {
        float4 bv = *(const float4*)(bias + te4);
        const float* bf = (const float*)&bv;
#pragma unroll
        for (int i = 0; i < 4; i++) {
            float2 a0 = unpk(acc[i][0]);
            float2 a1 = unpk(acc[i][1]);
            float* row = sm + (tm4 + i) * (NE + 4);
            row[te4 + 0] = a0.x + bf[0];
            row[te4 + 1] = a0.y + bf[1];
            row[te4 + 2] = a1.x + bf[2];
            row[te4 + 3] = a1.y + bf[3];
        }
    }
    __syncthreads();

    // one thread per token: softmax + top-2
    if (tid < MT) {
        const float* row = sm + tid * (NE + 4);
        float v1 = -3.402823466e38f; int i1 = 0;
        float v2 = -3.402823466e38f; int i2 = 0;
#pragma unroll 8
        for (int e = 0; e < NE; e++) {
            float v = row[e];
            if (v > v1)      { v2 = v1; i2 = i1; v1 = v; i1 = e; }
            else if (v > v2) { v2 = v;  i2 = e; }
        }
        float s = 0.f;
#pragma unroll 8
        for (int e = 0; e < NE; e++) s += __expf(row[e] - v1);
        float p1 = 1.0f / s;
        float p2 = __expf(v2 - v1) / s;

        int g = m0 + tid;
        out[2 * g + 0] = (float)i1;
        out[2 * g + 1] = (float)i2;
        size_t voff = (size_t)2 * M;
        out[voff + 2 * g + 0] = p1;
        out[voff + 2 * g + 1] = p2;
    }
}

extern "C" void kernel_launch(void* const* d_in, const int* in_sizes, int n_in,
                              void* d_out, int out_size) {
    const float* x  = (const float*)d_in[0];
    const float* W  = (const float*)d_in[1];
    const float* b  = (const float*)d_in[2];
    float* out = (float*)d_out;

    int M = in_sizes[0] / DK;   // 16384 tokens
    const int smem_bytes = 16384 * sizeof(float);   // 64 KiB
    cudaFuncSetAttribute(router_kernel,
                         cudaFuncAttributeMaxDynamicSharedMemorySize, smem_bytes);
    dim3 grid(M / MT);
    router_kernel<<<grid, NTHREADS, smem_bytes>>>(x, W, b, out, M);
}

// round 6
// speedup vs baseline: 2.0458x; 2.0458x over previous
#include <cuda_runtime.h>
#include <cuda_fp16.h>
#include <cstdint>

// TopKRouter via mma.sync f16 (hi/lo split, 3-pass): logits = x@W + b ; softmax E=64 ; top-2
// x: (16384, 2048) fp32, W: (2048, 64) fp32, b: (64,)
// out f32: [0..2M) = topk_idx as float (M,2) ; [2M..4M) = topk_vals (M,2)

#define DK 2048
#define NE 64
#define KS 64                   // K per slab
#define MTILE 64                // tokens per CTA
#define NSLAB (DK / KS)         // 32
#define NTHREADS 128
#define SCALE_LO 2048.0f
#define INV_LO   4.8828125e-4f  // 2^-11

// smem: two buffers, each: Ah[64][64]f16 | Al | Bh[64][64]f16(k-major) | Bl  (8KB each)
#define BUF_BYTES 32768
#define OFF_AH 0
#define OFF_AL 8192
#define OFF_BH 16384
#define OFF_BL 24576
#define OFF_BIAS (2 * BUF_BYTES)
#define SMEM_TOTAL (OFF_BIAS + 256)

#define SWZ(a) ((a) ^ (((a) >> 3) & 0x70))

__device__ uint16_t g_Wh[DK * NE];
__device__ uint16_t g_Wl[DK * NE];

__device__ __forceinline__ uint32_t su32(const void* p) {
    uint32_t a;
    asm("{ .reg .u64 t; cvta.to.shared.u64 t, %1; cvt.u32.u64 %0, t; }" : "=r"(a) : "l"(p));
    return a;
}
__device__ __forceinline__ void cp_async16(uint32_t saddr, const void* g) {
    asm volatile("cp.async.cg.shared.global [%0], [%1], 16;" :: "r"(saddr), "l"(g));
}
#define CP_COMMIT() asm volatile("cp.async.commit_group;" ::: "memory")
#define CP_WAIT0()  asm volatile("cp.async.wait_group 0;" ::: "memory")

__device__ __forceinline__ void split_h(float v, uint16_t& h, uint16_t& l) {
    __half hh = __float2half_rn(v);
    float r = (v - __half2float(hh)) * SCALE_LO;
    __half ll = __float2half_rn(r);
    h = __half_as_ushort(hh);
    l = __half_as_ushort(ll);
}

#define LDSM_X4(r0, r1, r2, r3, a)                                             \
    asm volatile("ldmatrix.sync.aligned.m8n8.x4.shared.b16 {%0,%1,%2,%3}, [%4];" \
                 : "=r"(r0), "=r"(r1), "=r"(r2), "=r"(r3) : "r"(a))
#define LDSM_X4T(r0, r1, r2, r3, a)                                            \
    asm volatile("ldmatrix.sync.aligned.m8n8.x4.trans.shared.b16 {%0,%1,%2,%3}, [%4];" \
                 : "=r"(r0), "=r"(r1), "=r"(r2), "=r"(r3) : "r"(a))

#define MMA16816(d, a0, a1, a2, a3, b0, b1)                                    \
    asm volatile("mma.sync.aligned.m16n8k16.row.col.f32.f16.f16.f32 "          \
                 "{%0,%1,%2,%3}, {%4,%5,%6,%7}, {%8,%9}, {%0,%1,%2,%3};"       \
                 : "+f"((d)[0]), "+f"((d)[1]), "+f"((d)[2]), "+f"((d)[3])      \
                 : "r"(a0), "r"(a1), "r"(a2), "r"(a3), "r"(b0), "r"(b1))

// ---- pre-pass: convert W (fp32) -> g_Wh/g_Wl (fp16 hi/lo, lo scaled 2^11) ----
__global__ void wconv_kernel(const float* __restrict__ W) {
    int i = (blockIdx.x * blockDim.x + threadIdx.x) * 4;
    float4 v = *(const float4*)(W + i);
    uint16_t h[4], l[4];
    split_h(v.x, h[0], l[0]); split_h(v.y, h[1], l[1]);
    split_h(v.z, h[2], l[2]); split_h(v.w, h[3], l[3]);
    *(uint2*)(g_Wh + i) = make_uint2((uint32_t)h[0] | ((uint32_t)h[1] << 16),
                                     (uint32_t)h[2] | ((uint32_t)h[3] << 16));
    *(uint2*)(g_Wl + i) = make_uint2((uint32_t)l[0] | ((uint32_t)l[1] << 16),
                                     (uint32_t)l[2] | ((uint32_t)l[3] << 16));
}

__device__ __forceinline__ void load_convert_A(const float* __restrict__ x,
                                               char* smem, int buf, int m0,
                                               int c, int tid) {
    float4 xa[8];
#pragma unroll
    for (int r = 0; r < 8; r++) {
        int lin = r * NTHREADS + tid;
        int m = lin >> 4, kq = lin & 15;
        xa[r] = *(const float4*)(x + (size_t)(m0 + m) * DK + c * KS + kq * 4);
    }
#pragma unroll
    for (int r = 0; r < 8; r++) {
        int lin = r * NTHREADS + tid;
        int m = lin >> 4, kq = lin & 15;
        uint16_t h[4], l[4];
        split_h(xa[r].x, h[0], l[0]); split_h(xa[r].y, h[1], l[1]);
        split_h(xa[r].z, h[2], l[2]); split_h(xa[r].w, h[3], l[3]);
        uint32_t off = SWZ((uint32_t)(m * 128 + kq * 8));
        char* base = smem + buf * BUF_BYTES;
        *(uint2*)(base + OFF_AH + off) =
            make_uint2((uint32_t)h[0] | ((uint32_t)h[1] << 16),
                       (uint32_t)h[2] | ((uint32_t)h[3] << 16));
        *(uint2*)(base + OFF_AL + off) =
            make_uint2((uint32_t)l[0] | ((uint32_t)l[1] << 16),
                       (uint32_t)l[2] | ((uint32_t)l[3] << 16));
    }
}

__device__ __forceinline__ void issue_B(uint32_t sb, int buf, int c, int tid) {
    uint32_t dst = sb + buf * BUF_BYTES;
#pragma unroll
    for (int r = 0; r < 4; r++) {
        int lin = r * NTHREADS + tid;
        int k = lin >> 3, q = lin & 7;
        uint32_t off = SWZ((uint32_t)(k * 128 + q * 16));
        size_t ge = (size_t)(c * KS + k) * NE + q * 8;   // in halves
        cp_async16(dst + OFF_BH + off, (const char*)g_Wh + ge * 2);
        cp_async16(dst + OFF_BL + off, (const char*)g_Wl + ge * 2);
    }
    CP_COMMIT();
}

__global__ __launch_bounds__(NTHREADS)
void router_kernel(const float* __restrict__ x,
                   const float* __restrict__ bias,
                   float* __restrict__ out,
                   int M)
{
    extern __shared__ char smem[];
    const uint32_t sb = su32(smem);
    const int tid = threadIdx.x;
    const int wid = tid >> 5;
    const int lid = tid & 31;
    const int m0  = blockIdx.x * MTILE;
    const int mbase = wid * 16;
    float* bias_sm = (float*)(smem + OFF_BIAS);

    if (tid < NE) bias_sm[tid] = bias[tid];

    float acch[8][4], accl[8][4];
#pragma unroll
    for (int j = 0; j < 8; j++)
#pragma unroll
        for (int i = 0; i < 4; i++) { acch[j][i] = 0.f; accl[j][i] = 0.f; }

    // prologue: slab 0 into buf 0
    issue_B(sb, 0, 0, tid);
    load_convert_A(x, smem, 0, m0, 0, tid);
    CP_WAIT0();
    __syncthreads();

    // lane-address components (per ldmatrix matrix-group)
    const int lr = lid & 7;        // row within 8x8
    const int lg = lid >> 3;       // matrix index 0..3

#pragma unroll 1
    for (int c = 0; c < NSLAB; ++c) {
        const int p = c & 1, q = p ^ 1;
        if (c + 1 < NSLAB) {
            issue_B(sb, q, c + 1, tid);
            load_convert_A(x, smem, q, m0, c + 1, tid);
        }

        const uint32_t bufb = sb + p * BUF_BYTES;
#pragma unroll
        for (int s = 0; s < 4; s++) {
            // A fragments (hi & lo)
            uint32_t a_off = SWZ((uint32_t)((mbase + (lg & 1) * 8 + lr) * 128
                                            + s * 32 + (lg >> 1) * 16));
            uint32_t ah0, ah1, ah2, ah3, al0, al1, al2, al3;
            LDSM_X4(ah0, ah1, ah2, ah3, bufb + OFF_AH + a_off);
            LDSM_X4(al0, al1, al2, al3, bufb + OFF_AL + a_off);

            // B fragments: 4 trans-x4 per (hi,lo), each covers two n-tiles
            uint32_t bh[16], bl[16];
#pragma unroll
            for (int j2 = 0; j2 < 4; j2++) {
                uint32_t b_off = SWZ((uint32_t)((s * 16 + (lg & 1) * 8 + lr) * 128
                                                + (j2 * 16 + (lg >> 1) * 8) * 2));
                LDSM_X4T(bh[j2 * 4 + 0], bh[j2 * 4 + 1], bh[j2 * 4 + 2], bh[j2 * 4 + 3],
                         bufb + OFF_BH + b_off);
                LDSM_X4T(bl[j2 * 4 + 0], bl[j2 * 4 + 1], bl[j2 * 4 + 2], bl[j2 * 4 + 3],
                         bufb + OFF_BL + b_off);
            }
#pragma unroll
            for (int j = 0; j < 8; j++) {
                uint32_t b0h = bh[(j >> 1) * 4 + (j & 1) * 2];
                uint32_t b1h = bh[(j >> 1) * 4 + (j & 1) * 2 + 1];
                uint32_t b0l = bl[(j >> 1) * 4 + (j & 1) * 2];
                uint32_t b1l = bl[(j >> 1) * 4 + (j & 1) * 2 + 1];
                MMA16816(acch[j], ah0, ah1, ah2, ah3, b0h, b1h);
                MMA16816(accl[j], ah0, ah1, ah2, ah3, b0l, b1l);
                MMA16816(accl[j], al0, al1, al2, al3, b0h, b1h);
            }
        }

        if (c + 1 < NSLAB) CP_WAIT0();
        __syncthreads();
    }

    // ---- epilogue: combine, softmax, top-2 (quad-shuffle reduce) ----
    const int qr = lid >> 2;    // token row 0..7
    const int qc = lid & 3;
    float L0[16], L1[16];
#pragma unroll
    for (int j = 0; j < 8; j++) {
        int nb = j * 8 + qc * 2;
        L0[j * 2 + 0] = acch[j][0] + accl[j][0] * INV_LO + bias_sm[nb];
        L0[j * 2 + 1] = acch[j][1] + accl[j][1] * INV_LO + bias_sm[nb + 1];
        L1[j * 2 + 0] = acch[j][2] + accl[j][2] * INV_LO + bias_sm[nb];
        L1[j * 2 + 1] = acch[j][3] + accl[j][3] * INV_LO + bias_sm[nb + 1];
    }

#pragma unroll
    for (int t = 0; t < 2; t++) {
        const float* L = t ? L1 : L0;
        float v1 = -3.402823466e38f, v2 = -3.402823466e38f;
        int i1 = 0, i2 = 0;
#pragma unroll
        for (int u = 0; u < 16; u++) {
            int e = (u >> 1) * 8 + qc * 2 + (u & 1);
            float v = L[u];
            if (v > v1)      { v2 = v1; i2 = i1; v1 = v; i1 = e; }
            else if (v > v2) { v2 = v;  i2 = e; }
        }
        // merge across the 4 lanes of the quad
#pragma unroll
        for (int d = 1; d <= 2; d <<= 1) {
            float w1 = __shfl_xor_sync(0xffffffffu, v1, d);
            int   j1 = __shfl_xor_sync(0xffffffffu, i1, d);
            float w2 = __shfl_xor_sync(0xffffffffu, v2, d);
            int   j2 = __shfl_xor_sync(0xffffffffu, i2, d);
            float c2v; int c2i;
            if (w1 > v1) { c2v = v1; c2i = i1; v1 = w1; i1 = j1; }
            else         { c2v = w1; c2i = j1; }
            if (c2v > v2) { v2 = c2v; i2 = c2i; }
            if (w2 > v2)  { v2 = w2;  i2 = j2; }
        }
        float s = 0.f;
#pragma unroll
        for (int u = 0; u < 16; u++) s += __expf(L[u] - v1);
#pragma unroll
        for (int d = 1; d <= 2; d <<= 1) s += __shfl_xor_sync(0xffffffffu, s, d);

        if (qc == 0) {
            int g = m0 + mbase + qr + t * 8;
            out[2 * g + 0] = (float)i1;
            out[2 * g + 1] = (float)i2;
            size_t voff = (size_t)2 * M;
            out[voff + 2 * g + 0] = 1.0f / s;
            out[voff + 2 * g + 1] = __expf(v2 - v1) / s;
        }
    }
}

extern "C" void kernel_launch(void* const* d_in, const int* in_sizes, int n_in,
                              void* d_out, int out_size) {
    const float* x  = (const float*)d_in[0];
    const float* W  = (const float*)d_in[1];
    const float* b  = (const float*)d_in[2];
    float* out = (float*)d_out;

    int M = in_sizes[0] / DK;   // 16384
    wconv_kernel<<<(DK * NE / 4 + 255) / 256, 256>>>(W);
    cudaFuncSetAttribute(router_kernel,
                         cudaFuncAttributeMaxDynamicSharedMemorySize, SMEM_TOTAL);
    router_kernel<<<M / MTILE, NTHREADS, SMEM_TOTAL>>>(x, b, out, M);
}

// round 7
// speedup vs baseline: 4.0033x; 1.9568x over previous
#include <cuda_runtime.h>
#include <cuda_fp16.h>
#include <cstdint>

// TopKRouter via mma.sync f16 (hi/lo split, 3-pass): logits = x@W + b ; softmax E=64 ; top-2
// x: (16384, 2048) fp32, W: (2048, 64) fp32, b: (64,)
// out f32: [0..2M) = topk_idx as float (M,2) ; [2M..4M) = topk_vals (M,2)
// R7: MTILE=32 (grid 512), K-split warp pairs, LDG issue / convert split around compute.

#define DK 2048
#define NE 64
#define KS 64
#define MTILE 32
#define NSLAB (DK / KS)         // 32
#define NTHREADS 128
#define SCALE_LO 2048.0f
#define INV_LO   4.8828125e-4f  // 2^-11

#define BUF_BYTES 24576
#define OFF_AH 0
#define OFF_AL 4096
#define OFF_BH 8192
#define OFF_BL 16384
#define OFF_BIAS (2 * BUF_BYTES)
#define SMEM_TOTAL (OFF_BIAS + 512)

#define SWZ(a) ((a) ^ (((a) >> 3) & 0x70))

__device__ uint16_t g_Wh[DK * NE];
__device__ uint16_t g_Wl[DK * NE];

__device__ __forceinline__ uint32_t su32(const void* p) {
    uint32_t a;
    asm("{ .reg .u64 t; cvta.to.shared.u64 t, %1; cvt.u32.u64 %0, t; }" : "=r"(a) : "l"(p));
    return a;
}
__device__ __forceinline__ void cp_async16(uint32_t saddr, const void* g) {
    asm volatile("cp.async.cg.shared.global [%0], [%1], 16;" :: "r"(saddr), "l"(g));
}
#define CP_COMMIT() asm volatile("cp.async.commit_group;" ::: "memory")
#define CP_WAIT0()  asm volatile("cp.async.wait_group 0;" ::: "memory")

__device__ __forceinline__ void split_h(float v, uint16_t& h, uint16_t& l) {
    __half hh = __float2half_rn(v);
    float r = (v - __half2float(hh)) * SCALE_LO;
    __half ll = __float2half_rn(r);
    h = __half_as_ushort(hh);
    l = __half_as_ushort(ll);
}

#define LDSM_X4(r0, r1, r2, r3, a)                                             \
    asm volatile("ldmatrix.sync.aligned.m8n8.x4.shared.b16 {%0,%1,%2,%3}, [%4];" \
                 : "=r"(r0), "=r"(r1), "=r"(r2), "=r"(r3) : "r"(a))
#define LDSM_X4T(r0, r1, r2, r3, a)                                            \
    asm volatile("ldmatrix.sync.aligned.m8n8.x4.trans.shared.b16 {%0,%1,%2,%3}, [%4];" \
                 : "=r"(r0), "=r"(r1), "=r"(r2), "=r"(r3) : "r"(a))

#define MMA16816(d, a0, a1, a2, a3, b0, b1)                                    \
    asm volatile("mma.sync.aligned.m16n8k16.row.col.f32.f16.f16.f32 "          \
                 "{%0,%1,%2,%3}, {%4,%5,%6,%7}, {%8,%9}, {%0,%1,%2,%3};"       \
                 : "+f"((d)[0]), "+f"((d)[1]), "+f"((d)[2]), "+f"((d)[3])      \
                 : "r"(a0), "r"(a1), "r"(a2), "r"(a3), "r"(b0), "r"(b1))

__global__ void wconv_kernel(const float* __restrict__ W) {
    int i = (blockIdx.x * blockDim.x + threadIdx.x) * 4;
    float4 v = *(const float4*)(W + i);
    uint16_t h[4], l[4];
    split_h(v.x, h[0], l[0]); split_h(v.y, h[1], l[1]);
    split_h(v.z, h[2], l[2]); split_h(v.w, h[3], l[3]);
    *(uint2*)(g_Wh + i) = make_uint2((uint32_t)h[0] | ((uint32_t)h[1] << 16),
                                     (uint32_t)h[2] | ((uint32_t)h[3] << 16));
    *(uint2*)(g_Wl + i) = make_uint2((uint32_t)l[0] | ((uint32_t)l[1] << 16),
                                     (uint32_t)l[2] | ((uint32_t)l[3] << 16));
}

__device__ __forceinline__ void issue_A(const float* __restrict__ x, float4* xa,
                                        int m0, int c, int tid) {
#pragma unroll
    for (int r = 0; r < 4; r++) {
        int lin = r * NTHREADS + tid;
        int m = lin >> 4, kq = lin & 15;
        xa[r] = *(const float4*)(x + (size_t)(m0 + m) * DK + c * KS + kq * 4);
    }
}
__device__ __forceinline__ void store_A(char* smem, int buf, const float4* xa, int tid) {
    char* base = smem + buf * BUF_BYTES;
#pragma unroll
    for (int r = 0; r < 4; r++) {
        int lin = r * NTHREADS + tid;
        int m = lin >> 4, kq = lin & 15;
        uint16_t h[4], l[4];
        split_h(xa[r].x, h[0], l[0]); split_h(xa[r].y, h[1], l[1]);
        split_h(xa[r].z, h[2], l[2]); split_h(xa[r].w, h[3], l[3]);
        uint32_t off = SWZ((uint32_t)(m * 128 + kq * 8));
        *(uint2*)(base + OFF_AH + off) =
            make_uint2((uint32_t)h[0] | ((uint32_t)h[1] << 16),
                       (uint32_t)h[2] | ((uint32_t)h[3] << 16));
        *(uint2*)(base + OFF_AL + off) =
            make_uint2((uint32_t)l[0] | ((uint32_t)l[1] << 16),
                       (uint32_t)l[2] | ((uint32_t)l[3] << 16));
    }
}
__device__ __forceinline__ void issue_B(uint32_t sb, int buf, int c, int tid) {
    uint32_t dst = sb + buf * BUF_BYTES;
#pragma unroll
    for (int r = 0; r < 4; r++) {
        int lin = r * NTHREADS + tid;
        int k = lin >> 3, q = lin & 7;
        uint32_t off = SWZ((uint32_t)(k * 128 + q * 16));
        size_t ge = (size_t)(c * KS + k) * NE + q * 8;
        cp_async16(dst + OFF_BH + off, (const char*)g_Wh + ge * 2);
        cp_async16(dst + OFF_BL + off, (const char*)g_Wl + ge * 2);
    }
    CP_COMMIT();
}

__global__ __launch_bounds__(NTHREADS)
void router_kernel(const float* __restrict__ x,
                   const float* __restrict__ bias,
                   float* __restrict__ out,
                   int M)
{
    extern __shared__ char smem[];
    const uint32_t sb = su32(smem);
    const int tid = threadIdx.x;
    const int wid = tid >> 5;
    const int lid = tid & 31;
    const int m0  = blockIdx.x * MTILE;
    const int mhalf = wid & 1;      // which 16-token half
    const int khalf = wid >> 1;     // which 32-k half of each slab
    float* bias_sm = (float*)(smem + OFF_BIAS);

    if (tid < NE) bias_sm[tid] = bias[tid];

    float acch[8][4], accl[8][4];
#pragma unroll
    for (int j = 0; j < 8; j++)
#pragma unroll
        for (int i = 0; i < 4; i++) { acch[j][i] = 0.f; accl[j][i] = 0.f; }

    float4 xa[4];
    issue_B(sb, 0, 0, tid);
    issue_A(x, xa, m0, 0, tid);
    store_A(smem, 0, xa, tid);
    CP_WAIT0();
    __syncthreads();

    const int lr = lid & 7;
    const int lg = lid >> 3;

#pragma unroll 1
    for (int c = 0; c < NSLAB; ++c) {
        const int p = c & 1, q = p ^ 1;
        const bool more = (c + 1 < NSLAB);
        if (more) {
            issue_B(sb, q, c + 1, tid);
            issue_A(x, xa, m0, c + 1, tid);
        }

        const uint32_t bufb = sb + p * BUF_BYTES;
#pragma unroll
        for (int s = 0; s < 2; s++) {
            uint32_t a_off = SWZ((uint32_t)((mhalf * 16 + (lg & 1) * 8 + lr) * 128
                                            + khalf * 64 + s * 32 + (lg >> 1) * 16));
            uint32_t ah0, ah1, ah2, ah3, al0, al1, al2, al3;
            LDSM_X4(ah0, ah1, ah2, ah3, bufb + OFF_AH + a_off);
            LDSM_X4(al0, al1, al2, al3, bufb + OFF_AL + a_off);

            uint32_t bh[16], bl[16];
#pragma unroll
            for (int j2 = 0; j2 < 4; j2++) {
                uint32_t b_off = SWZ((uint32_t)((khalf * 32 + s * 16 + (lg & 1) * 8 + lr) * 128
                                                + (j2 * 16 + (lg >> 1) * 8) * 2));
                LDSM_X4T(bh[j2 * 4 + 0], bh[j2 * 4 + 1], bh[j2 * 4 + 2], bh[j2 * 4 + 3],
                         bufb + OFF_BH + b_off);
                LDSM_X4T(bl[j2 * 4 + 0], bl[j2 * 4 + 1], bl[j2 * 4 + 2], bl[j2 * 4 + 3],
                         bufb + OFF_BL + b_off);
            }
#pragma unroll
            for (int j = 0; j < 8; j++) {
                uint32_t b0h = bh[(j >> 1) * 4 + (j & 1) * 2];
                uint32_t b1h = bh[(j >> 1) * 4 + (j & 1) * 2 + 1];
                uint32_t b0l = bl[(j >> 1) * 4 + (j & 1) * 2];
                uint32_t b1l = bl[(j >> 1) * 4 + (j & 1) * 2 + 1];
                MMA16816(acch[j], ah0, ah1, ah2, ah3, b0h, b1h);
                MMA16816(accl[j], ah0, ah1, ah2, ah3, b0l, b1l);
                MMA16816(accl[j], al0, al1, al2, al3, b0h, b1h);
            }
        }

        if (more) { store_A(smem, q, xa, tid); CP_WAIT0(); }
        __syncthreads();
    }

    // ---- epilogue: combine hi/lo, exchange K-halves via smem, softmax + top-2 ----
    const int qr = lid >> 2;
    const int qc = lid & 3;
    float L[2][16];
#pragma unroll
    for (int j = 0; j < 8; j++) {
        L[0][j * 2 + 0] = acch[j][0] + accl[j][0] * INV_LO;
        L[0][j * 2 + 1] = acch[j][1] + accl[j][1] * INV_LO;
        L[1][j * 2 + 0] = acch[j][2] + accl[j][2] * INV_LO;
        L[1][j * 2 + 1] = acch[j][3] + accl[j][3] * INV_LO;
    }

    float* ex = (float*)smem;          // [32 tokens][66] K-half exchange
    if (khalf == 1) {
#pragma unroll
        for (int t = 0; t < 2; t++) {
            int token = mhalf * 16 + t * 8 + qr;
#pragma unroll
            for (int j = 0; j < 8; j++) {
                int e = j * 8 + qc * 2;
                *(float2*)&ex[token * 66 + e] = make_float2(L[t][j * 2], L[t][j * 2 + 1]);
            }
        }
    }
    __syncthreads();

    if (khalf == 0) {
#pragma unroll
        for (int t = 0; t < 2; t++) {
            int token = mhalf * 16 + t * 8 + qr;
            float Lf[16];
#pragma unroll
            for (int j = 0; j < 8; j++) {
                int e = j * 8 + qc * 2;
                float2 o = *(const float2*)&ex[token * 66 + e];
                Lf[j * 2 + 0] = L[t][j * 2 + 0] + o.x + bias_sm[e];
                Lf[j * 2 + 1] = L[t][j * 2 + 1] + o.y + bias_sm[e + 1];
            }
            float v1 = -3.402823466e38f, v2 = -3.402823466e38f;
            int i1 = 0, i2 = 0;
#pragma unroll
            for (int u = 0; u < 16; u++) {
                int e = (u >> 1) * 8 + qc * 2 + (u & 1);
                float v = Lf[u];
                if (v > v1)      { v2 = v1; i2 = i1; v1 = v; i1 = e; }
                else if (v > v2) { v2 = v;  i2 = e; }
            }
#pragma unroll
            for (int d = 1; d <= 2; d <<= 1) {
                float w1 = __shfl_xor_sync(0xffffffffu, v1, d);
                int   j1 = __shfl_xor_sync(0xffffffffu, i1, d);
                float w2 = __shfl_xor_sync(0xffffffffu, v2, d);
                int   j2 = __shfl_xor_sync(0xffffffffu, i2, d);
                float c2v; int c2i;
                if (w1 > v1) { c2v = v1; c2i = i1; v1 = w1; i1 = j1; }
                else         { c2v = w1; c2i = j1; }
                if (c2v > v2) { v2 = c2v; i2 = c2i; }
                if (w2 > v2)  { v2 = w2;  i2 = j2; }
            }
            float s = 0.f;
#pragma unroll
            for (int u = 0; u < 16; u++) s += __expf(Lf[u] - v1);
#pragma unroll
            for (int d = 1; d <= 2; d <<= 1) s += __shfl_xor_sync(0xffffffffu, s, d);

            if (qc == 0) {
                int g = m0 + token;
                out[2 * g + 0] = (float)i1;
                out[2 * g + 1] = (float)i2;
                size_t voff = (size_t)2 * M;
                out[voff + 2 * g + 0] = 1.0f / s;
                out[voff + 2 * g + 1] = __expf(v2 - v1) / s;
            }
        }
    }
}

extern "C" void kernel_launch(void* const* d_in, const int* in_sizes, int n_in,
                              void* d_out, int out_size) {
    const float* x  = (const float*)d_in[0];
    const float* W  = (const float*)d_in[1];
    const float* b  = (const float*)d_in[2];
    float* out = (float*)d_out;

    int M = in_sizes[0] / DK;   // 16384
    wconv_kernel<<<(DK * NE / 4 + 255) / 256, 256>>>(W);
    cudaFuncSetAttribute(router_kernel,
                         cudaFuncAttributeMaxDynamicSharedMemorySize, SMEM_TOTAL);
    router_kernel<<<M / MTILE, NTHREADS, SMEM_TOTAL>>>(x, b, out, M);
}